// round 3
// baseline (speedup 1.0000x reference)
#include <cuda_runtime.h>
#include <cstdint>

// Shapes: B=256, T=512, IN=128, H=256, W1=W2=512. M = B*T = 131072.
#define NRNN 128  // persistent CTAs for the recurrence (1 per SM, <=148)

// ---------------- static device scratch (no allocation allowed) ------------
__device__ float g_buf1[131072u * 512u];   // input-MLP act1; later reused for attn weights
__device__ float g_buf2[131072u * 512u];   // input-MLP act2
__device__ float g_xin [512u * 65536u];    // xin_t  [T][B][H]
__device__ float g_hs  [512u * 65536u];    // hidden states [T][B][H]
__device__ float g_h0  [65536];
__device__ float g_a1  [256 * 512];
__device__ float g_a2  [256 * 512];
__device__ unsigned g_cnt;
__device__ unsigned g_gen;

// ---------------------------------------------------------------------------
// Big fp32 SGEMM: C = act(A[M,K] @ W[K,N] + bias). 128x64 tile, BK=16,
// 256 threads, 8x4 per thread. ACT: 0 none, 1 relu, 2 exp(tanh()).
// PERM: 0 row-major store; 1 scatter row (b*T+t) -> [t][b][:] for xin_t.
// ---------------------------------------------------------------------------
template <int ACT, int PERM>
__global__ __launch_bounds__(256) void sgemm(
    const float* __restrict__ A, const float* __restrict__ W,
    const float* __restrict__ bias, float* __restrict__ C,
    int M, int N, int K)
{
    __shared__ float As[16 * 132];   // k-major [k][row], padded
    __shared__ float Bs[16 * 68];    // [k][col], padded

    const int nb = N >> 6;
    const int bm = (int)(blockIdx.x / nb) << 7;
    const int bn = (int)(blockIdx.x % nb) << 6;
    const int tid = threadIdx.x;
    const int tx = tid & 15;      // 16 col-groups of 4
    const int ty = tid >> 4;      // 16 row-groups of 8

    float acc[8][4];
#pragma unroll
    for (int i = 0; i < 8; i++)
#pragma unroll
        for (int j = 0; j < 4; j++) acc[i][j] = 0.f;

    for (int p = 0; p < K; p += 16) {
        // A tile 128x16: 512 float4, 2 per thread, transposed to k-major
#pragma unroll
        for (int i = 0; i < 2; i++) {
            int f = tid + (i << 8);
            int row = f >> 2;
            int kc = (f & 3) << 2;
            float4 v = *reinterpret_cast<const float4*>(
                A + (size_t)(bm + row) * K + p + kc);
            As[(kc + 0) * 132 + row] = v.x;
            As[(kc + 1) * 132 + row] = v.y;
            As[(kc + 2) * 132 + row] = v.z;
            As[(kc + 3) * 132 + row] = v.w;
        }
        // B tile 16x64: 256 float4, 1 per thread
        {
            int k  = tid >> 4;
            int c4 = (tid & 15) << 2;
            *reinterpret_cast<float4*>(&Bs[k * 68 + c4]) =
                *reinterpret_cast<const float4*>(W + (size_t)(p + k) * N + bn + c4);
        }
        __syncthreads();
#pragma unroll
        for (int k = 0; k < 16; k++) {
            float av[8], bv[4];
            *reinterpret_cast<float4*>(&av[0]) =
                *reinterpret_cast<float4*>(&As[k * 132 + (ty << 3)]);
            *reinterpret_cast<float4*>(&av[4]) =
                *reinterpret_cast<float4*>(&As[k * 132 + (ty << 3) + 4]);
            *reinterpret_cast<float4*>(&bv[0]) =
                *reinterpret_cast<float4*>(&Bs[k * 68 + (tx << 2)]);
#pragma unroll
            for (int i = 0; i < 8; i++)
#pragma unroll
                for (int j = 0; j < 4; j++) acc[i][j] += av[i] * bv[j];
        }
        __syncthreads();
    }

#pragma unroll
    for (int i = 0; i < 8; i++) {
        int r = bm + (ty << 3) + i;
#pragma unroll
        for (int j = 0; j < 4; j++) {
            int c = bn + (tx << 2) + j;
            float v = acc[i][j] + bias[c];
            if (ACT == 1) v = fmaxf(v, 0.f);
            if (ACT == 2) v = __expf(tanhf(v));
            if (PERM == 0) {
                C[(size_t)r * N + c] = v;
            } else {
                int b = r >> 9;          // r = b*T + t, T=512
                int t = r & 511;
                C[((size_t)t << 16) + (b << 8) + c] = v;  // [t][b][c], B*H=65536
            }
        }
    }
}

// ---------------------------------------------------------------------------
// Grid-wide barrier for the persistent RNN kernel (read gen BEFORE arriving).
// ---------------------------------------------------------------------------
__device__ __forceinline__ void grid_sync()
{
    __syncthreads();
    if (threadIdx.x == 0) {
        volatile unsigned* gv = &g_gen;
        unsigned gen = *gv;
        __threadfence();
        if (atomicAdd(&g_cnt, 1u) == NRNN - 1) {
            g_cnt = 0;
            __threadfence();
            atomicAdd(&g_gen, 1u);
        } else {
            while (*gv == gen) { __nanosleep(64); }
        }
    }
    __syncthreads();
}

// ---------------------------------------------------------------------------
// One layer of the recurrent MLP inside the persistent kernel.
// 128 CTAs x 128 threads. Tile: TM=32 rows x TN cols; 16 col-tiles, 8 row-tiles.
// TN=32 -> 4x2 per thread; TN=16 -> 2x2 per thread. K chunked by 64 via smem.
// Activations (A, output) cross CTAs between barriers -> __ldcg loads.
// MODE: 0 relu -> C ; 1 tanh(v + xin) -> C.
// ---------------------------------------------------------------------------
template <int TN, int KTOT, int MODE>
__device__ void layer_gemm(float* sm,
    const float* A, int lda,
    const float* __restrict__ W, int ldw,
    const float* __restrict__ bias,
    float* C, int ldc, const float* xin)
{
    float* As = sm;               // [64][36] k-major (rows padded to 36)
    float* Bs = sm + 64 * 36;     // [64][TN+4]
    constexpr int RM = TN / 8;    // 4 or 2
    constexpr int CP = TN / 2;    // col pairs
    constexpr int BSTR = TN + 4;

    const int tid = threadIdx.x;
    const int ct  = blockIdx.x;
    const int bm  = (ct >> 4) * 32;
    const int bn  = (ct & 15) * TN;
    const int r0  = (tid / CP) * RM;
    const int c0  = (tid % CP) * 2;

    float acc[RM][2];
#pragma unroll
    for (int i = 0; i < RM; i++) { acc[i][0] = 0.f; acc[i][1] = 0.f; }

    for (int kc = 0; kc < KTOT; kc += 64) {
        // As: 32 rows x 64 k = 512 float4, 4 per thread (ldcg: cross-CTA data)
#pragma unroll
        for (int i = 0; i < 4; i++) {
            int s = tid + i * 128;
            int row = s >> 4;
            int kq = (s & 15) << 2;
            float4 v = __ldcg(reinterpret_cast<const float4*>(
                A + (size_t)(bm + row) * lda + kc + kq));
            As[(kq + 0) * 36 + row] = v.x;
            As[(kq + 1) * 36 + row] = v.y;
            As[(kq + 2) * 36 + row] = v.z;
            As[(kq + 3) * 36 + row] = v.w;
        }
        // Bs: 64 k x TN cols = 16*TN float4, TN/8 per thread (weights, ro)
#pragma unroll
        for (int i = 0; i < TN / 8; i++) {
            int s = tid + i * 128;
            int k  = s / (TN / 4);
            int cq = (s % (TN / 4)) << 2;
            *reinterpret_cast<float4*>(&Bs[k * BSTR + cq]) =
                __ldg(reinterpret_cast<const float4*>(
                    W + (size_t)(kc + k) * ldw + bn + cq));
        }
        __syncthreads();
#pragma unroll 8
        for (int k = 0; k < 64; k++) {
            float2 b = *reinterpret_cast<float2*>(&Bs[k * BSTR + c0]);
            float a[RM];
            if (RM == 4)
                *reinterpret_cast<float4*>(a) =
                    *reinterpret_cast<float4*>(&As[k * 36 + r0]);
            else
                *reinterpret_cast<float2*>(a) =
                    *reinterpret_cast<float2*>(&As[k * 36 + r0]);
#pragma unroll
            for (int i = 0; i < RM; i++) {
                acc[i][0] += a[i] * b.x;
                acc[i][1] += a[i] * b.y;
            }
        }
        __syncthreads();
    }

#pragma unroll
    for (int i = 0; i < RM; i++) {
        int r = bm + r0 + i;
#pragma unroll
        for (int j = 0; j < 2; j++) {
            int c = bn + c0 + j;
            float v = acc[i][j] + bias[c];
            if (MODE == 0) v = fmaxf(v, 0.f);
            else           v = tanhf(v + __ldg(&xin[r * 256 + c]));
            C[(size_t)r * ldc + c] = v;
        }
    }
}

__global__ __launch_bounds__(128, 1) void rnn_kernel(
    const float* __restrict__ W1, const float* __restrict__ b1,
    const float* __restrict__ W2, const float* __restrict__ b2,
    const float* __restrict__ W3, const float* __restrict__ b3)
{
    __shared__ float sm[64 * 36 + 64 * 36];   // 18.4 KB, shared by all layers

    // zero h0
    for (int i = threadIdx.x + blockIdx.x * 128; i < 65536; i += 128 * NRNN)
        g_h0[i] = 0.f;
    grid_sync();

    for (int t = 0; t < 512; t++) {
        const float* hp = t ? (g_hs + (size_t)(t - 1) * 65536) : g_h0;
        layer_gemm<32, 256, 0>(sm, hp,   256, W1, 512, b1, g_a1, 512, nullptr);
        grid_sync();
        layer_gemm<32, 512, 0>(sm, g_a1, 512, W2, 512, b2, g_a2, 512, nullptr);
        grid_sync();
        layer_gemm<16, 512, 1>(sm, g_a2, 512, W3, 256, b3,
                               g_hs + (size_t)t * 65536, 256,
                               g_xin + (size_t)t * 65536);
        grid_sync();
    }
}

// ---------------------------------------------------------------------------
// Attention pool: out[b][h] = sum_t aw*hs / sum_t aw  (aw already exp'd)
// ---------------------------------------------------------------------------
__global__ __launch_bounds__(256) void pool_kernel(
    const float* __restrict__ aw, const float* __restrict__ hs,
    float* __restrict__ out)
{
    int i = blockIdx.x * 256 + threadIdx.x;   // i = b*256 + h, 65536 total
    float num = 0.f, den = 0.f;
#pragma unroll 4
    for (int t = 0; t < 512; t++) {
        float a = __ldg(&aw[(size_t)t * 65536 + i]);
        float h = __ldg(&hs[(size_t)t * 65536 + i]);
        num += a * h;
        den += a;
    }
    out[i] = num / den;
}

// ---------------------------------------------------------------------------
extern "C" void kernel_launch(void* const* d_in, const int* in_sizes, int n_in,
                              void* d_out, int out_size)
{
    const float* x    = (const float*)d_in[0];
    const float* h_w1 = (const float*)d_in[1];
    const float* h_b1 = (const float*)d_in[2];
    const float* h_w2 = (const float*)d_in[3];
    const float* h_b2 = (const float*)d_in[4];
    const float* h_w3 = (const float*)d_in[5];
    const float* h_b3 = (const float*)d_in[6];
    const float* i_w1 = (const float*)d_in[7];
    const float* i_b1 = (const float*)d_in[8];
    const float* i_w2 = (const float*)d_in[9];
    const float* i_b2 = (const float*)d_in[10];
    const float* i_w3 = (const float*)d_in[11];
    const float* i_b3 = (const float*)d_in[12];
    const float* att_w = (const float*)d_in[13];
    const float* att_b = (const float*)d_in[14];
    float* out = (float*)d_out;

    float *buf1, *buf2, *xin, *hs;
    cudaGetSymbolAddress((void**)&buf1, g_buf1);
    cudaGetSymbolAddress((void**)&buf2, g_buf2);
    cudaGetSymbolAddress((void**)&xin,  g_xin);
    cudaGetSymbolAddress((void**)&hs,   g_hs);

    const int M = 131072;

    // Input MLP: x -> relu -> relu -> xin_t (scatter to [T][B][H])
    sgemm<1, 0><<<(M / 128) * (512 / 64), 256>>>(x,    i_w1, i_b1, buf1, M, 512, 128);
    sgemm<1, 0><<<(M / 128) * (512 / 64), 256>>>(buf1, i_w2, i_b2, buf2, M, 512, 512);
    sgemm<0, 1><<<(M / 128) * (256 / 64), 256>>>(buf2, i_w3, i_b3, xin,  M, 256, 512);

    // Recurrence: persistent kernel over all 512 steps
    rnn_kernel<<<NRNN, 128>>>(h_w1, h_b1, h_w2, h_b2, h_w3, h_b3);

    // Attention weights: exp(tanh(hs @ att_w + att_b)) -> buf1 (reused)
    sgemm<2, 0><<<(M / 128) * (256 / 64), 256>>>(hs, att_w, att_b, buf1, M, 256, 256);

    // Pool over T
    pool_kernel<<<256, 256>>>(buf1, hs, out);
}